// round 10
// baseline (speedup 1.0000x reference)
#include <cuda_runtime.h>
#include <cuda_fp16.h>
#include <math.h>

#define Nn 50000
#define Ee 800000
#define NEG_SLOPE 0.2f
#define W_STRIDE 132   // ==4 (mod 32) -> conflict-free quad-banks for float4 LDS
#define NB 196         // ceil(Nn/256) scan blocks

// ---------------- static device scratch (no allocations allowed) ----------------
__device__ __half  g_hproj16[Nn * 128];   // fp16 projected features [n][head*32+o]
__device__ float4 g_ssrc[Nn];             // s_src per node, 4 heads (fp32)
__device__ float4 g_sdst[Nn];             // s_dst per node, 4 heads (fp32)
__device__ int    g_count[Nn];            // zero-init'd; self-restores to zero each run
__device__ int    g_offset[Nn + 1];
__device__ int    g_blocksum[NB];
__device__ int    g_srcsorted[Ee];

// packed fp32x2 FMA (Blackwell FFMA2 — 2x fp32 throughput, only reachable via PTX)
__device__ __forceinline__ void fma_x2(unsigned long long& d,
                                       unsigned long long a,
                                       unsigned long long b) {
    asm("fma.rn.f32x2 %0, %1, %2, %0;" : "+l"(d) : "l"(a), "l"(b));
}
__device__ __forceinline__ unsigned long long pack2(float lo, float hi) {
    unsigned long long r;
    asm("mov.b64 %0, {%1, %2};" : "=l"(r) : "f"(lo), "f"(hi));
    return r;
}

// ---------------- K1: projection + attention pre-scores (2 cols/thread, FFMA2) --------
// block = 128 threads = 4 warps.
//   warpHalf = wid&1  -> which 64 output cols (heads 2*warpHalf, 2*warpHalf+1)
//   warpPair = wid>>1 -> which 4 node-pairs of the 16-node group
// Each h LDS.128 (broadcast) feeds 4 FFMA2 (2 cols x 2 packed nodes).
extern __shared__ float k1_smem[];
__global__ void __launch_bounds__(128) k_proj(const float* __restrict__ h,
                                              const float* __restrict__ W,
                                              const float* __restrict__ a) {
    float*  sW  = k1_smem;                       // 4*32*132 = 16896 floats
    float2* sh2 = (float2*)(k1_smem + 16896);    // 8 pairs * 128 float2 = 8192 B
    const int t = threadIdx.x;
    const int wid = t >> 5, lane = t & 31;
    const int warpHalf = wid & 1;
    const int warpPair = wid >> 1;
    const int head0 = warpHalf * 2, head1 = head0 + 1;

    // stage W transposed: sW[(head*32+o)*132 + k]
    for (int i = t; i < 16384; i += 128) {
        int hh = i >> 12; int k = (i >> 5) & 127; int oo = i & 31;
        sW[((hh << 5) | oo) * W_STRIDE + k] = W[i];
    }
    const float asrc0 = a[head0 * 64 + lane];
    const float adst0 = a[head0 * 64 + 32 + lane];
    const float asrc1 = a[head1 * 64 + lane];
    const float adst1 = a[head1 * 64 + 32 + lane];
    __syncthreads();

    const float* wp0 = sW + (head0 * 32 + lane) * W_STRIDE;
    const float* wp1 = sW + (head1 * 32 + lane) * W_STRIDE;
    const int pb = warpPair * 4;                 // this warp's first node-pair

    const int NGROUPS = Nn / 16;  // 3125 exactly
    for (int g = blockIdx.x; g < NGROUPS; g += gridDim.x) {
        const int n0 = g * 16;
        __syncthreads();   // protect sh2 reuse
        #pragma unroll
        for (int p = 0; p < 8; p++) {
            float lo = h[(n0 + 2 * p)     * 128 + t];
            float hi = h[(n0 + 2 * p + 1) * 128 + t];
            sh2[p * 128 + t] = make_float2(lo, hi);
        }
        __syncthreads();

        unsigned long long acc[4][2];
        #pragma unroll
        for (int p = 0; p < 4; p++) { acc[p][0] = 0ull; acc[p][1] = 0ull; }

        #pragma unroll 2
        for (int k4 = 0; k4 < 128; k4 += 4) {
            const float4 fw0 = *(const float4*)(wp0 + k4);
            const float4 fw1 = *(const float4*)(wp1 + k4);
            const unsigned long long w00 = pack2(fw0.x, fw0.x);
            const unsigned long long w01 = pack2(fw0.y, fw0.y);
            const unsigned long long w02 = pack2(fw0.z, fw0.z);
            const unsigned long long w03 = pack2(fw0.w, fw0.w);
            const unsigned long long w10 = pack2(fw1.x, fw1.x);
            const unsigned long long w11 = pack2(fw1.y, fw1.y);
            const unsigned long long w12 = pack2(fw1.z, fw1.z);
            const unsigned long long w13 = pack2(fw1.w, fw1.w);
            #pragma unroll
            for (int p = 0; p < 4; p++) {
                const ulonglong2* base = (const ulonglong2*)(sh2 + (pb + p) * 128 + k4);
                ulonglong2 q0 = base[0];
                ulonglong2 q1 = base[1];
                fma_x2(acc[p][0], q0.x, w00);
                fma_x2(acc[p][0], q0.y, w01);
                fma_x2(acc[p][0], q1.x, w02);
                fma_x2(acc[p][0], q1.y, w03);
                fma_x2(acc[p][1], q0.x, w10);
                fma_x2(acc[p][1], q0.y, w11);
                fma_x2(acc[p][1], q1.x, w12);
                fma_x2(acc[p][1], q1.y, w13);
            }
        }

        #pragma unroll
        for (int p = 0; p < 4; p++) {
            const int nA = n0 + (pb + p) * 2;
            const int nB = nA + 1;
            float2 a0 = *(const float2*)&acc[p][0];   // col0: (nA, nB)
            float2 a1 = *(const float2*)&acc[p][1];   // col1: (nA, nB)
            const int col0 = head0 * 32 + lane;
            const int col1 = head1 * 32 + lane;
            g_hproj16[nA * 128 + col0] = __float2half_rn(a0.x);
            g_hproj16[nB * 128 + col0] = __float2half_rn(a0.y);
            g_hproj16[nA * 128 + col1] = __float2half_rn(a1.x);
            g_hproj16[nB * 128 + col1] = __float2half_rn(a1.y);

            float v0 = a0.x * asrc0, v1 = a0.x * adst0;
            float v2 = a0.y * asrc0, v3 = a0.y * adst0;
            float v4 = a1.x * asrc1, v5 = a1.x * adst1;
            float v6 = a1.y * asrc1, v7 = a1.y * adst1;
            #pragma unroll
            for (int off = 16; off; off >>= 1) {
                v0 += __shfl_xor_sync(0xffffffffu, v0, off);
                v1 += __shfl_xor_sync(0xffffffffu, v1, off);
                v2 += __shfl_xor_sync(0xffffffffu, v2, off);
                v3 += __shfl_xor_sync(0xffffffffu, v3, off);
                v4 += __shfl_xor_sync(0xffffffffu, v4, off);
                v5 += __shfl_xor_sync(0xffffffffu, v5, off);
                v6 += __shfl_xor_sync(0xffffffffu, v6, off);
                v7 += __shfl_xor_sync(0xffffffffu, v7, off);
            }
            if (lane == 0) {
                ((float*)&g_ssrc[nA])[head0] = v0;
                ((float*)&g_sdst[nA])[head0] = v1;
                ((float*)&g_ssrc[nB])[head0] = v2;
                ((float*)&g_sdst[nB])[head0] = v3;
                ((float*)&g_ssrc[nA])[head1] = v4;
                ((float*)&g_sdst[nA])[head1] = v5;
                ((float*)&g_ssrc[nB])[head1] = v6;
                ((float*)&g_sdst[nB])[head1] = v7;
            }
        }
    }
}

// ---------------- K2: in-degree histogram ----------------
__global__ void k_hist(const int* __restrict__ dst) {
    int e = blockIdx.x * blockDim.x + threadIdx.x;
    if (e < Ee) atomicAdd(&g_count[dst[e]], 1);
}

// ---------------- K3a: per-block local exclusive scan ----------------
__global__ void __launch_bounds__(256) k_scan_local() {
    __shared__ int sh[256];
    const int b = blockIdx.x, t = threadIdx.x;
    const int i = b * 256 + t;
    int v = (i < Nn) ? g_count[i] : 0;
    sh[t] = v;
    __syncthreads();
    #pragma unroll
    for (int off = 1; off < 256; off <<= 1) {
        int u = (t >= off) ? sh[t - off] : 0;
        __syncthreads();
        sh[t] += u;
        __syncthreads();
    }
    if (i < Nn) g_offset[i] = sh[t] - v;       // exclusive within block
    if (t == 255) g_blocksum[b] = sh[255];
}

// ---------------- K3b: each block redundantly scans the 196 block sums, adds its offset ---
__global__ void __launch_bounds__(256) k_scan_add() {
    __shared__ int sh[256];
    const int b = blockIdx.x, t = threadIdx.x;
    int v = (t < NB) ? g_blocksum[t] : 0;
    sh[t] = v;
    __syncthreads();
    #pragma unroll
    for (int off = 1; off < 256; off <<= 1) {
        int u = (t >= off) ? sh[t - off] : 0;
        __syncthreads();
        sh[t] += u;
        __syncthreads();
    }
    const int myoff = (b == 0) ? 0 : sh[b - 1];   // exclusive prefix for this block
    const int i = b * 256 + t;
    if (i < Nn) g_offset[i] += myoff;
    if (b == NB - 1 && t == 0) g_offset[Nn] = sh[NB - 1];  // grand total == Ee
}

// ---------------- K4: scatter src indices into dst-sorted order ----------------
// Uses g_count itself as the cursor (atomicSub) -> g_count self-restores to zero.
__global__ void k_scatter(const int* __restrict__ src, const int* __restrict__ dst) {
    int e = blockIdx.x * blockDim.x + threadIdx.x;
    if (e >= Ee) return;
    int d = dst[e];
    int pos = g_offset[d] + atomicSub(&g_count[d], 1) - 1;
    g_srcsorted[pos] = src[e];
}

// ---------------- K5: per-node softmax + aggregation, single pass, no max needed ----------
// exp() without max subtraction is safe: scores ~ N(0, ~1.8^2), max over 800K ~ 9.5,
// exp(9.5) ~ 1.3e4 << fp32 range; alpha is shift-invariant so this matches the reference.
// Device globals referenced directly (NOT as host args — ATS host-shadow trap on GB300).
__global__ void __launch_bounds__(256) k_aggregate(float* __restrict__ out) {
    const int lane = threadIdx.x & 31;
    const int wIdx = threadIdx.x >> 5;
    const int n = blockIdx.x * 8 + wIdx;   // grid sized so n < Nn always
    const int beg = g_offset[n];
    const int end = g_offset[n + 1];

    __shared__ float4 s_w[8][32];
    __shared__ int    s_s[8][32];

    const float4 sd = g_sdst[n];

    float4 acc = make_float4(0.f, 0.f, 0.f, 0.f);
    float4 sw  = make_float4(0.f, 0.f, 0.f, 0.f);
    const int hsel = lane >> 3;   // my 4 output elems all belong to head = lane/8

    for (int base = beg; base < end; base += 32) {
        int e = base + lane;
        float4 w = make_float4(0.f, 0.f, 0.f, 0.f);
        int sv = 0;
        if (e < end) {
            sv = g_srcsorted[e];
            float4 ss = g_ssrc[sv];
            float v;
            v = ss.x + sd.x; v = v > 0.f ? v : NEG_SLOPE * v; w.x = __expf(v);
            v = ss.y + sd.y; v = v > 0.f ? v : NEG_SLOPE * v; w.y = __expf(v);
            v = ss.z + sd.z; v = v > 0.f ? v : NEG_SLOPE * v; w.z = __expf(v);
            v = ss.w + sd.w; v = v > 0.f ? v : NEG_SLOPE * v; w.w = __expf(v);
        }
        sw.x += w.x; sw.y += w.y; sw.z += w.z; sw.w += w.w;
        s_w[wIdx][lane] = w;
        s_s[wIdx][lane] = sv;
        __syncwarp();
        const int cnt = min(32, end - base);

        // unroll by 4: batch 4 independent gathers for MLP over L2 latency
        int j = 0;
        for (; j + 4 <= cnt; j += 4) {
            float wj0 = ((const float*)&s_w[wIdx][j + 0])[hsel];
            float wj1 = ((const float*)&s_w[wIdx][j + 1])[hsel];
            float wj2 = ((const float*)&s_w[wIdx][j + 2])[hsel];
            float wj3 = ((const float*)&s_w[wIdx][j + 3])[hsel];
            const __half2* p0 = (const __half2*)(g_hproj16 + s_s[wIdx][j + 0] * 128 + lane * 4);
            const __half2* p1 = (const __half2*)(g_hproj16 + s_s[wIdx][j + 1] * 128 + lane * 4);
            const __half2* p2 = (const __half2*)(g_hproj16 + s_s[wIdx][j + 2] * 128 + lane * 4);
            const __half2* p3 = (const __half2*)(g_hproj16 + s_s[wIdx][j + 3] * 128 + lane * 4);
            __half2 a0 = p0[0], b0 = p0[1];
            __half2 a1 = p1[0], b1 = p1[1];
            __half2 a2 = p2[0], b2 = p2[1];
            __half2 a3 = p3[0], b3 = p3[1];
            float2 f;
            f = __half22float2(a0); acc.x = fmaf(wj0, f.x, acc.x); acc.y = fmaf(wj0, f.y, acc.y);
            f = __half22float2(b0); acc.z = fmaf(wj0, f.x, acc.z); acc.w = fmaf(wj0, f.y, acc.w);
            f = __half22float2(a1); acc.x = fmaf(wj1, f.x, acc.x); acc.y = fmaf(wj1, f.y, acc.y);
            f = __half22float2(b1); acc.z = fmaf(wj1, f.x, acc.z); acc.w = fmaf(wj1, f.y, acc.w);
            f = __half22float2(a2); acc.x = fmaf(wj2, f.x, acc.x); acc.y = fmaf(wj2, f.y, acc.y);
            f = __half22float2(b2); acc.z = fmaf(wj2, f.x, acc.z); acc.w = fmaf(wj2, f.y, acc.w);
            f = __half22float2(a3); acc.x = fmaf(wj3, f.x, acc.x); acc.y = fmaf(wj3, f.y, acc.y);
            f = __half22float2(b3); acc.z = fmaf(wj3, f.x, acc.z); acc.w = fmaf(wj3, f.y, acc.w);
        }
        for (; j < cnt; j++) {
            float wj = ((const float*)&s_w[wIdx][j])[hsel];
            const __half2* hp2 = (const __half2*)(g_hproj16 + s_s[wIdx][j] * 128 + lane * 4);
            float2 f0 = __half22float2(hp2[0]);
            float2 f1 = __half22float2(hp2[1]);
            acc.x = fmaf(wj, f0.x, acc.x);
            acc.y = fmaf(wj, f0.y, acc.y);
            acc.z = fmaf(wj, f1.x, acc.z);
            acc.w = fmaf(wj, f1.y, acc.w);
        }
        __syncwarp();
    }

    // denom per head, then normalize + ELU
    #pragma unroll
    for (int off = 16; off; off >>= 1) {
        sw.x += __shfl_xor_sync(0xffffffffu, sw.x, off);
        sw.y += __shfl_xor_sync(0xffffffffu, sw.y, off);
        sw.z += __shfl_xor_sync(0xffffffffu, sw.z, off);
        sw.w += __shfl_xor_sync(0xffffffffu, sw.w, off);
    }
    float denom = (hsel == 0) ? sw.x : (hsel == 1) ? sw.y : (hsel == 2) ? sw.z : sw.w;
    float inv = 1.0f / fmaxf(denom, 1e-16f);

    float4 o4;
    float x;
    x = acc.x * inv; o4.x = x > 0.f ? x : expm1f(x);
    x = acc.y * inv; o4.y = x > 0.f ? x : expm1f(x);
    x = acc.z * inv; o4.z = x > 0.f ? x : expm1f(x);
    x = acc.w * inv; o4.w = x > 0.f ? x : expm1f(x);
    *(float4*)(out + n * 128 + lane * 4) = o4;
}

// ---------------- launcher ----------------
extern "C" void kernel_launch(void* const* d_in, const int* in_sizes, int n_in,
                              void* d_out, int out_size) {
    const float* h  = (const float*)d_in[0];
    const int*   ei = (const int*)d_in[1];    // [2][E]
    const float* W  = (const float*)d_in[2];
    const float* a  = (const float*)d_in[3];
    float* out = (float*)d_out;

    const int* src = ei;
    const int* dst = ei + Ee;

    const int k1_smem_bytes = (16896 + 2048) * sizeof(float);  // 75776
    // Not stream-ordered; capture-safe and idempotent.
    cudaFuncSetAttribute(k_proj, cudaFuncAttributeMaxDynamicSharedMemorySize, k1_smem_bytes);

    k_proj<<<296, 128, k1_smem_bytes>>>(h, W, a);
    k_hist<<<(Ee + 255) / 256, 256>>>(dst);
    k_scan_local<<<NB, 256>>>();
    k_scan_add<<<NB, 256>>>();
    k_scatter<<<(Ee + 255) / 256, 256>>>(src, dst);
    k_aggregate<<<Nn / 8, 256>>>(out);
}

// round 11
// speedup vs baseline: 1.3092x; 1.3092x over previous
#include <cuda_runtime.h>
#include <cuda_fp16.h>
#include <math.h>

#define Nn 50000
#define Ee 800000
#define NEG_SLOPE 0.2f
#define W_STRIDE 129   // odd stride -> conflict-free smem for transposed W
#define NB 196         // ceil(Nn/256) scan blocks
#define PROJ_GRID 444  // 148 SMs x 3 blocks (70KB smem each)
#define EPB ((Ee + PROJ_GRID - 1) / PROJ_GRID)   // 1802 edges per proj block (hist slice)

// ---------------- static device scratch (no allocations allowed) ----------------
__device__ __half  g_hproj16[Nn * 128];   // fp16 projected features [n][head*32+o]
__device__ float4 g_ssrc[Nn];             // s_src per node, 4 heads (fp32)
__device__ float4 g_sdst[Nn];             // s_dst per node, 4 heads (fp32)
__device__ int    g_count[Nn];            // zero-init'd; self-restores to zero each run
__device__ int    g_offset[Nn + 1];
__device__ int    g_blocksum[NB];
__device__ int    g_srcsorted[Ee];

// packed fp32x2 FMA (Blackwell FFMA2 — 2x fp32 throughput, only reachable via PTX)
__device__ __forceinline__ void fma_x2(unsigned long long& d,
                                       unsigned long long a,
                                       unsigned long long b) {
    asm("fma.rn.f32x2 %0, %1, %2, %0;" : "+l"(d) : "l"(a), "l"(b));
}
__device__ __forceinline__ unsigned long long pack2(float lo, float hi) {
    unsigned long long r;
    asm("mov.b64 %0, {%1, %2};" : "=l"(r) : "f"(lo), "f"(hi));
    return r;
}

// ---------------- K1: projection + attention pre-scores + fused degree histogram -------
// block = 128 threads; thread t owns column (head = t>>5, o = t&31).
// W transposed in smem: sW[(head*32+o)*129 + k].
// h staged as 4 node-PAIRS packed float2: sh2[p*128 + k] = (h[n0+2p][k], h[n0+2p+1][k]).
// Histogram slice (independent of proj math) runs first, overlapping atomic latency.
extern __shared__ float k1_smem[];
__global__ void __launch_bounds__(128) k_proj(const float* __restrict__ h,
                                              const float* __restrict__ W,
                                              const float* __restrict__ a,
                                              const int* __restrict__ dst) {
    float*  sW  = k1_smem;                       // 16512 floats
    float2* sh2 = (float2*)(k1_smem + 16512);    // 4*128 float2 = 1024 floats
    const int t = threadIdx.x;
    const int head = t >> 5, o = t & 31;

    // stage W transposed
    for (int i = t; i < 16384; i += 128) {
        int hh = i >> 12; int k = (i >> 5) & 127; int oo = i & 31;
        sW[((hh << 5) | oo) * W_STRIDE + k] = W[i];
    }
    const float asrc = a[head * 64 + o];
    const float adst = a[head * 64 + 32 + o];

    // fused in-degree histogram: this block's edge slice
    {
        const int e0 = blockIdx.x * EPB;
        const int e1 = min(e0 + EPB, Ee);
        for (int e = e0 + t; e < e1; e += 128)
            atomicAdd(&g_count[dst[e]], 1);
    }
    __syncthreads();

    const float* wp = sW + t * W_STRIDE;
    const int NGROUPS = Nn / 8;  // 6250 exactly
    for (int g = blockIdx.x; g < NGROUPS; g += gridDim.x) {
        const int n0 = g * 8;
        __syncthreads();   // protect sh2 reuse
        #pragma unroll
        for (int p = 0; p < 4; p++) {
            float lo = h[(n0 + 2 * p)     * 128 + t];
            float hi = h[(n0 + 2 * p + 1) * 128 + t];
            sh2[p * 128 + t] = make_float2(lo, hi);
        }
        __syncthreads();

        unsigned long long acc[4];
        #pragma unroll
        for (int p = 0; p < 4; p++) acc[p] = 0ull;

        #pragma unroll 2
        for (int k4 = 0; k4 < 128; k4 += 4) {
            const unsigned long long w0 = pack2(wp[k4],     wp[k4]);
            const unsigned long long w1 = pack2(wp[k4 + 1], wp[k4 + 1]);
            const unsigned long long w2 = pack2(wp[k4 + 2], wp[k4 + 2]);
            const unsigned long long w3 = pack2(wp[k4 + 3], wp[k4 + 3]);
            #pragma unroll
            for (int p = 0; p < 4; p++) {
                const ulonglong2* base = (const ulonglong2*)(sh2 + p * 128 + k4);
                ulonglong2 q0 = base[0];
                ulonglong2 q1 = base[1];
                fma_x2(acc[p], q0.x, w0);
                fma_x2(acc[p], q0.y, w1);
                fma_x2(acc[p], q1.x, w2);
                fma_x2(acc[p], q1.y, w3);
            }
        }
        #pragma unroll
        for (int p = 0; p < 4; p++) {
            float2 av = *(const float2*)&acc[p];
            #pragma unroll
            for (int half = 0; half < 2; half++) {
                const int r = 2 * p + half;
                const float accr = half ? av.y : av.x;
                g_hproj16[(n0 + r) * 128 + t] = __float2half_rn(accr);
                float ps = accr * asrc;
                float pd = accr * adst;
                #pragma unroll
                for (int off = 16; off; off >>= 1) {
                    ps += __shfl_xor_sync(0xffffffffu, ps, off);
                    pd += __shfl_xor_sync(0xffffffffu, pd, off);
                }
                if (o == 0) {
                    ((float*)&g_ssrc[n0 + r])[head] = ps;
                    ((float*)&g_sdst[n0 + r])[head] = pd;
                }
            }
        }
    }
}

// ---------------- K3a: per-block local exclusive scan ----------------
__global__ void __launch_bounds__(256) k_scan_local() {
    __shared__ int sh[256];
    const int b = blockIdx.x, t = threadIdx.x;
    const int i = b * 256 + t;
    int v = (i < Nn) ? g_count[i] : 0;
    sh[t] = v;
    __syncthreads();
    #pragma unroll
    for (int off = 1; off < 256; off <<= 1) {
        int u = (t >= off) ? sh[t - off] : 0;
        __syncthreads();
        sh[t] += u;
        __syncthreads();
    }
    if (i < Nn) g_offset[i] = sh[t] - v;       // exclusive within block
    if (t == 255) g_blocksum[b] = sh[255];
}

// ---------------- K3b: each block redundantly scans the 196 block sums, adds its offset ---
__global__ void __launch_bounds__(256) k_scan_add() {
    __shared__ int sh[256];
    const int b = blockIdx.x, t = threadIdx.x;
    int v = (t < NB) ? g_blocksum[t] : 0;
    sh[t] = v;
    __syncthreads();
    #pragma unroll
    for (int off = 1; off < 256; off <<= 1) {
        int u = (t >= off) ? sh[t - off] : 0;
        __syncthreads();
        sh[t] += u;
        __syncthreads();
    }
    const int myoff = (b == 0) ? 0 : sh[b - 1];   // exclusive prefix for this block
    const int i = b * 256 + t;
    if (i < Nn) g_offset[i] += myoff;
    if (b == NB - 1 && t == 0) g_offset[Nn] = sh[NB - 1];  // grand total == Ee
}

// ---------------- K4: scatter src indices into dst-sorted order ----------------
// Uses g_count itself as the cursor (atomicSub) -> g_count self-restores to zero.
__global__ void k_scatter(const int* __restrict__ src, const int* __restrict__ dst) {
    int e = blockIdx.x * blockDim.x + threadIdx.x;
    if (e >= Ee) return;
    int d = dst[e];
    int pos = g_offset[d] + atomicSub(&g_count[d], 1) - 1;
    g_srcsorted[pos] = src[e];
}

// ---------------- K5: per-node softmax + aggregation, single pass, no max needed ----------
// exp() without max subtraction is safe: scores ~ N(0, ~1.8^2), max over 800K ~ 9.5,
// exp(9.5) ~ 1.3e4 << fp32 range; alpha is shift-invariant so this matches the reference.
// Device globals referenced directly (NOT as host args — ATS host-shadow trap on GB300).
__global__ void __launch_bounds__(256) k_aggregate(float* __restrict__ out) {
    const int lane = threadIdx.x & 31;
    const int wIdx = threadIdx.x >> 5;
    const int n = blockIdx.x * 8 + wIdx;   // grid sized so n < Nn always
    const int beg = g_offset[n];
    const int end = g_offset[n + 1];

    __shared__ float4 s_w[8][32];
    __shared__ int    s_s[8][32];

    const float4 sd = g_sdst[n];

    float4 acc = make_float4(0.f, 0.f, 0.f, 0.f);
    float4 sw  = make_float4(0.f, 0.f, 0.f, 0.f);
    const int hsel = lane >> 3;   // my 4 output elems all belong to head = lane/8

    for (int base = beg; base < end; base += 32) {
        int e = base + lane;
        float4 w = make_float4(0.f, 0.f, 0.f, 0.f);
        int sv = 0;
        if (e < end) {
            sv = g_srcsorted[e];
            float4 ss = g_ssrc[sv];
            float v;
            v = ss.x + sd.x; v = v > 0.f ? v : NEG_SLOPE * v; w.x = __expf(v);
            v = ss.y + sd.y; v = v > 0.f ? v : NEG_SLOPE * v; w.y = __expf(v);
            v = ss.z + sd.z; v = v > 0.f ? v : NEG_SLOPE * v; w.z = __expf(v);
            v = ss.w + sd.w; v = v > 0.f ? v : NEG_SLOPE * v; w.w = __expf(v);
        }
        sw.x += w.x; sw.y += w.y; sw.z += w.z; sw.w += w.w;
        s_w[wIdx][lane] = w;
        s_s[wIdx][lane] = sv;
        __syncwarp();
        const int cnt = min(32, end - base);

        // unroll by 4: batch 4 independent gathers for MLP over L2 latency
        int j = 0;
        for (; j + 4 <= cnt; j += 4) {
            float wj0 = ((const float*)&s_w[wIdx][j + 0])[hsel];
            float wj1 = ((const float*)&s_w[wIdx][j + 1])[hsel];
            float wj2 = ((const float*)&s_w[wIdx][j + 2])[hsel];
            float wj3 = ((const float*)&s_w[wIdx][j + 3])[hsel];
            const __half2* p0 = (const __half2*)(g_hproj16 + s_s[wIdx][j + 0] * 128 + lane * 4);
            const __half2* p1 = (const __half2*)(g_hproj16 + s_s[wIdx][j + 1] * 128 + lane * 4);
            const __half2* p2 = (const __half2*)(g_hproj16 + s_s[wIdx][j + 2] * 128 + lane * 4);
            const __half2* p3 = (const __half2*)(g_hproj16 + s_s[wIdx][j + 3] * 128 + lane * 4);
            __half2 a0 = p0[0], b0 = p0[1];
            __half2 a1 = p1[0], b1 = p1[1];
            __half2 a2 = p2[0], b2 = p2[1];
            __half2 a3 = p3[0], b3 = p3[1];
            float2 f;
            f = __half22float2(a0); acc.x = fmaf(wj0, f.x, acc.x); acc.y = fmaf(wj0, f.y, acc.y);
            f = __half22float2(b0); acc.z = fmaf(wj0, f.x, acc.z); acc.w = fmaf(wj0, f.y, acc.w);
            f = __half22float2(a1); acc.x = fmaf(wj1, f.x, acc.x); acc.y = fmaf(wj1, f.y, acc.y);
            f = __half22float2(b1); acc.z = fmaf(wj1, f.x, acc.z); acc.w = fmaf(wj1, f.y, acc.w);
            f = __half22float2(a2); acc.x = fmaf(wj2, f.x, acc.x); acc.y = fmaf(wj2, f.y, acc.y);
            f = __half22float2(b2); acc.z = fmaf(wj2, f.x, acc.z); acc.w = fmaf(wj2, f.y, acc.w);
            f = __half22float2(a3); acc.x = fmaf(wj3, f.x, acc.x); acc.y = fmaf(wj3, f.y, acc.y);
            f = __half22float2(b3); acc.z = fmaf(wj3, f.x, acc.z); acc.w = fmaf(wj3, f.y, acc.w);
        }
        for (; j < cnt; j++) {
            float wj = ((const float*)&s_w[wIdx][j])[hsel];
            const __half2* hp2 = (const __half2*)(g_hproj16 + s_s[wIdx][j] * 128 + lane * 4);
            float2 f0 = __half22float2(hp2[0]);
            float2 f1 = __half22float2(hp2[1]);
            acc.x = fmaf(wj, f0.x, acc.x);
            acc.y = fmaf(wj, f0.y, acc.y);
            acc.z = fmaf(wj, f1.x, acc.z);
            acc.w = fmaf(wj, f1.y, acc.w);
        }
        __syncwarp();
    }

    // denom per head, then normalize + ELU
    #pragma unroll
    for (int off = 16; off; off >>= 1) {
        sw.x += __shfl_xor_sync(0xffffffffu, sw.x, off);
        sw.y += __shfl_xor_sync(0xffffffffu, sw.y, off);
        sw.z += __shfl_xor_sync(0xffffffffu, sw.z, off);
        sw.w += __shfl_xor_sync(0xffffffffu, sw.w, off);
    }
    float denom = (hsel == 0) ? sw.x : (hsel == 1) ? sw.y : (hsel == 2) ? sw.z : sw.w;
    float inv = 1.0f / fmaxf(denom, 1e-16f);

    float4 o4;
    float x;
    x = acc.x * inv; o4.x = x > 0.f ? x : expm1f(x);
    x = acc.y * inv; o4.y = x > 0.f ? x : expm1f(x);
    x = acc.z * inv; o4.z = x > 0.f ? x : expm1f(x);
    x = acc.w * inv; o4.w = x > 0.f ? x : expm1f(x);
    *(float4*)(out + n * 128 + lane * 4) = o4;
}

// ---------------- launcher ----------------
extern "C" void kernel_launch(void* const* d_in, const int* in_sizes, int n_in,
                              void* d_out, int out_size) {
    const float* h  = (const float*)d_in[0];
    const int*   ei = (const int*)d_in[1];    // [2][E]
    const float* W  = (const float*)d_in[2];
    const float* a  = (const float*)d_in[3];
    float* out = (float*)d_out;

    const int* src = ei;
    const int* dst = ei + Ee;

    const int k1_smem_bytes = (16512 + 1024) * sizeof(float);  // 70144
    // Not stream-ordered; capture-safe and idempotent.
    cudaFuncSetAttribute(k_proj, cudaFuncAttributeMaxDynamicSharedMemorySize, k1_smem_bytes);

    k_proj<<<PROJ_GRID, 128, k1_smem_bytes>>>(h, W, a, dst);
    k_scan_local<<<NB, 256>>>();
    k_scan_add<<<NB, 256>>>();
    k_scatter<<<(Ee + 255) / 256, 256>>>(src, dst);
    k_aggregate<<<Nn / 8, 256>>>(out);
}